// round 16
// baseline (speedup 1.0000x reference)
#include <cuda_runtime.h>

// ConstantCurrentLIFEncoder: 100 steps of LIF dynamics with constant input.
//   v' = v + 0.1f * ((0 - v) + I);  z = (v' - 1 > 0);  v = v' - z*v'
// Input:  [64, 8192] f32. Output: [100, 64, 8192] f32 spikes (210 MB).
//
// R16: fork-join overlap of R15's two nodes.
//   - memset node: zero background, 210 MB at ~6.85 TB/s (~30.7us) — the
//     driver fill path, measured faster than any SM store kernel (5.75 TB/s).
//   - guard kernel (CONCURRENT, second stream): reads I only; raises a
//     __device__ flag iff any lane has I >= 1.0f (could ever spike). Never
//     writes d_out, so no race with the memset. For I < 1, fp32 rounding
//     gives v_t = I(1-0.9^t) <= I < 1 = v_th forever -> zero spikes, the
//     memset background is exact.
//   - fallback kernel (after join): one broadcast flag load; early-exit when
//     0 (~2us). If 1 (never for this input), runs the exact 100-step
//     simulation with stores over the background — generic correctness.
// Streams/events created lazily on the first (correctness, pre-capture)
// call; the captured graph is identical on every replay.

#define N_ELEMS   524288
#define N_VEC     (N_ELEMS / 4)   // 131072 float4 lanes
#define SEQ_LEN   100
#define OUT_ELEMS (100 * N_ELEMS)

__device__ int g_spike_possible = 0;

__global__ void __launch_bounds__(256)
lif_guard_kernel(const float* __restrict__ in) {
    const int idx = blockIdx.x * blockDim.x + threadIdx.x;  // float4 lane
    const float4 I = __ldg(reinterpret_cast<const float4*>(in) + idx);

    // Raise flag iff some component could ever reach threshold.
    if (!(I.x < 1.0f && I.y < 1.0f && I.z < 1.0f && I.w < 1.0f)) {
        atomicOr(&g_spike_possible, 1);
    }
}

__global__ void __launch_bounds__(256)
lif_fallback_kernel(const float* __restrict__ in, float* __restrict__ out) {
    // Broadcast load; all threads exit immediately when no spikes possible.
    if (g_spike_possible == 0) return;

    // Generic path (never taken for this input): exact reference recurrence,
    // store all 100 timesteps over the memset background.
    const int idx = blockIdx.x * blockDim.x + threadIdx.x;
    const float4 I = __ldg(reinterpret_cast<const float4*>(in) + idx);

    float vx = 0.0f, vy = 0.0f, vz = 0.0f, vw = 0.0f;
    float4* o = reinterpret_cast<float4*>(out) + idx;

    for (int t = 0; t < SEQ_LEN; t++) {
        vx = vx + 0.1f * ((0.0f - vx) + I.x);
        vy = vy + 0.1f * ((0.0f - vy) + I.y);
        vz = vz + 0.1f * ((0.0f - vz) + I.z);
        vw = vw + 0.1f * ((0.0f - vw) + I.w);

        float4 s;
        s.x = (vx - 1.0f > 0.0f) ? 1.0f : 0.0f;
        s.y = (vy - 1.0f > 0.0f) ? 1.0f : 0.0f;
        s.z = (vz - 1.0f > 0.0f) ? 1.0f : 0.0f;
        s.w = (vw - 1.0f > 0.0f) ? 1.0f : 0.0f;

        vx = vx - s.x * vx;
        vy = vy - s.y * vy;
        vz = vz - s.z * vz;
        vw = vw - s.w * vw;

        o[(size_t)t * N_VEC] = s;
    }
}

extern "C" void kernel_launch(void* const* d_in, const int* in_sizes, int n_in,
                              void* d_out, int out_size) {
    const float* in = (const float*)d_in[0];
    float* out = (float*)d_out;

    // Lazily created once on the first (correctness, pre-capture) call.
    static cudaStream_t s2 = nullptr;
    static cudaEvent_t e_fork = nullptr, e_join = nullptr;
    if (s2 == nullptr) {
        cudaStreamCreateWithFlags(&s2, cudaStreamNonBlocking);
        cudaEventCreateWithFlags(&e_fork, cudaEventDisableTiming);
        cudaEventCreateWithFlags(&e_join, cudaEventDisableTiming);
    }

    // Fork: guard runs on s2 concurrently with the memset on the main stream.
    cudaEventRecord(e_fork, 0);
    cudaStreamWaitEvent(s2, e_fork, 0);
    lif_guard_kernel<<<512, 256, 0, s2>>>(in);
    cudaEventRecord(e_join, s2);

    // Main stream: zero background via the driver fill path (~6.85 TB/s).
    cudaMemsetAsync(out, 0, (size_t)OUT_ELEMS * sizeof(float), 0);

    // Join, then near-free fallback (early-exit when no spikes possible).
    cudaStreamWaitEvent(0, e_join, 0);
    lif_fallback_kernel<<<512, 256>>>(in, out);
}

// round 17
// speedup vs baseline: 1.0900x; 1.0900x over previous
#include <cuda_runtime.h>

// ConstantCurrentLIFEncoder: 100 steps of LIF dynamics with constant input.
//   v' = v + 0.1f * ((0 - v) + I);  z = (v' - 1 > 0);  v = v' - z*v'
// Input:  [64, 8192] f32. Output: [100, 64, 8192] f32 spikes (210 MB).
//
// R17: parallel split of the output write between the two fastest write
// engines measured on this chip:
//   s2 (SM stores, 5.75 TB/s): compute kernel writes t=0..24 exactly
//       (52.5 MB) and computes the spike-possible guard (any I >= 1.0f;
//       for I < 1, v_t = I(1-0.9^t) < 1 = v_th forever under fp32, so all
//       later spikes are zero).
//   s1 (driver fill path, 7.6 TB/s): memset zeros t=25..99 (157.5 MB),
//       then a fallback kernel that early-exits when the flag is 0 (~4us);
//       if set (never for this input), it simulates exactly and stores
//       t=25..99 over the background — ordered after the memset (same
//       stream) and after the guard (event), so no race.
// R16 lesson applied: NO real work on the legacy default stream (its
// implicit-sync semantics serialized all branches under capture). Stream 0
// carries only fork/join events.
// Flag protocol: sticky __device__ int, set-only via atomicOr. Never set for
// quiet inputs; a stale 1 only causes a redundant exact store pass (correct
// values), never corruption -> deterministic and safe without a reset node.

#define N_ELEMS   524288
#define N_VEC     (N_ELEMS / 4)   // 131072 float4 lanes
#define SEQ_LEN   100
#define T_SPLIT   25              // t < T_SPLIT written by SM kernel
#define OUT_ELEMS (100 * N_ELEMS)

__device__ int g_spike_possible = 0;

__global__ void __launch_bounds__(256)
lif_head_kernel(const float* __restrict__ in, float* __restrict__ out) {
    const int idx = blockIdx.x * blockDim.x + threadIdx.x;  // float4 lane
    const float4 I = __ldg(reinterpret_cast<const float4*>(in) + idx);

    // Guard: can any component ever reach threshold?
    if (!(I.x < 1.0f && I.y < 1.0f && I.z < 1.0f && I.w < 1.0f)) {
        atomicOr(&g_spike_possible, 1);
    }

    float vx = 0.0f, vy = 0.0f, vz = 0.0f, vw = 0.0f;
    float4* o = reinterpret_cast<float4*>(out) + idx;

    #pragma unroll 5
    for (int t = 0; t < T_SPLIT; t++) {
        vx = vx + 0.1f * ((0.0f - vx) + I.x);
        vy = vy + 0.1f * ((0.0f - vy) + I.y);
        vz = vz + 0.1f * ((0.0f - vz) + I.z);
        vw = vw + 0.1f * ((0.0f - vw) + I.w);

        float4 s;
        s.x = (vx - 1.0f > 0.0f) ? 1.0f : 0.0f;
        s.y = (vy - 1.0f > 0.0f) ? 1.0f : 0.0f;
        s.z = (vz - 1.0f > 0.0f) ? 1.0f : 0.0f;
        s.w = (vw - 1.0f > 0.0f) ? 1.0f : 0.0f;

        vx = vx - s.x * vx;
        vy = vy - s.y * vy;
        vz = vz - s.z * vz;
        vw = vw - s.w * vw;

        __stcs(o + (size_t)t * N_VEC, s);
    }
}

__global__ void __launch_bounds__(256)
lif_tail_fallback_kernel(const float* __restrict__ in, float* __restrict__ out) {
    // Early-exit when no lane can spike (always, for this input).
    if (g_spike_possible == 0) return;

    // Generic path: exact simulation; store t = T_SPLIT..99 over background.
    const int idx = blockIdx.x * blockDim.x + threadIdx.x;
    const float4 I = __ldg(reinterpret_cast<const float4*>(in) + idx);

    float vx = 0.0f, vy = 0.0f, vz = 0.0f, vw = 0.0f;
    float4* o = reinterpret_cast<float4*>(out) + idx;

    for (int t = 0; t < SEQ_LEN; t++) {
        vx = vx + 0.1f * ((0.0f - vx) + I.x);
        vy = vy + 0.1f * ((0.0f - vy) + I.y);
        vz = vz + 0.1f * ((0.0f - vz) + I.z);
        vw = vw + 0.1f * ((0.0f - vw) + I.w);

        float4 s;
        s.x = (vx - 1.0f > 0.0f) ? 1.0f : 0.0f;
        s.y = (vy - 1.0f > 0.0f) ? 1.0f : 0.0f;
        s.z = (vz - 1.0f > 0.0f) ? 1.0f : 0.0f;
        s.w = (vw - 1.0f > 0.0f) ? 1.0f : 0.0f;

        vx = vx - s.x * vx;
        vy = vy - s.y * vy;
        vz = vz - s.z * vz;
        vw = vw - s.w * vw;

        if (t >= T_SPLIT) {
            o[(size_t)t * N_VEC] = s;
        }
    }
}

extern "C" void kernel_launch(void* const* d_in, const int* in_sizes, int n_in,
                              void* d_out, int out_size) {
    const float* in = (const float*)d_in[0];
    float* out = (float*)d_out;

    // Lazily created once on the first (correctness, pre-capture) call.
    static cudaStream_t s1 = nullptr, s2 = nullptr;
    static cudaEvent_t e_fork = nullptr, e_guard = nullptr, e1 = nullptr, e2 = nullptr;
    if (s1 == nullptr) {
        cudaStreamCreateWithFlags(&s1, cudaStreamNonBlocking);
        cudaStreamCreateWithFlags(&s2, cudaStreamNonBlocking);
        cudaEventCreateWithFlags(&e_fork, cudaEventDisableTiming);
        cudaEventCreateWithFlags(&e_guard, cudaEventDisableTiming);
        cudaEventCreateWithFlags(&e1, cudaEventDisableTiming);
        cudaEventCreateWithFlags(&e2, cudaEventDisableTiming);
    }

    // Fork (stream 0 carries only events — R16 lesson: legacy-stream work
    // serializes all branches under capture).
    cudaEventRecord(e_fork, 0);
    cudaStreamWaitEvent(s1, e_fork, 0);
    cudaStreamWaitEvent(s2, e_fork, 0);

    // s2: SM writes t=0..24 exactly + guard flag.
    lif_head_kernel<<<512, 256, 0, s2>>>(in, out);
    cudaEventRecord(e_guard, s2);

    // s1: driver fill zeros t=25..99, then flag-gated fallback (ordered
    // after the memset by stream order and after the guard by event).
    cudaMemsetAsync(out + (size_t)T_SPLIT * N_ELEMS, 0,
                    (size_t)(SEQ_LEN - T_SPLIT) * N_ELEMS * sizeof(float), s1);
    cudaStreamWaitEvent(s1, e_guard, 0);
    lif_tail_fallback_kernel<<<512, 256, 0, s1>>>(in, out);

    // Join back onto stream 0.
    cudaEventRecord(e1, s1);
    cudaEventRecord(e2, s2);
    cudaStreamWaitEvent(0, e1, 0);
    cudaStreamWaitEvent(0, e2, 0);
}